// round 2
// baseline (speedup 1.0000x reference)
#include <cuda_runtime.h>
#include <math.h>
#include <stdint.h>

#define Bb 64
#define Cc 4
#define Nn 128
#define Kk 64

// Scratch (static device globals — no allocation).
__device__ uint32_t            g_masks[Bb * Cc * Nn * 4];        // [b][c][i][w]  512 KB
__device__ unsigned long long  g_sorted[Bb * Nn * Kk];           // [b][t][k]     4 MB

// ---------------------------------------------------------------------------
// Kernel 1 (fused): blocks [0,1024) pack adj bits; blocks [1024,1280) sort x.
// ---------------------------------------------------------------------------
__global__ __launch_bounds__(256, 4)
void gmp_prep(const float* __restrict__ x, const float* __restrict__ adj) {
    const int tid  = threadIdx.x;
    const int warp = tid >> 5;
    const int lane = tid & 31;

    if (blockIdx.x < 1024) {
        // ---- pack: 32 rows per block, 4 per warp ----
        #pragma unroll
        for (int r = 0; r < 4; ++r) {
            const int row = blockIdx.x * 32 + warp * 4 + r;   // (b*C+c)*N+i
            const float* ap = adj + (size_t)row * Nn;
            uint32_t m[4];
            #pragma unroll
            for (int q = 0; q < 4; ++q) {
                const float v = ap[q * 32 + lane];
                m[q] = __ballot_sync(0xffffffffu, v != 0.0f);
            }
            if (lane == 0)
                ((uint4*)g_masks)[row] = make_uint4(m[0], m[1], m[2], m[3]);
        }
    } else {
        // ---- sort: one block sorts 16 (b,k) columns of 128, descending ----
        __shared__ unsigned long long ss[Nn][17];   // pad 17 -> conflict-free
        const int sb = blockIdx.x - 1024;
        const int b  = sb >> 2;
        const int k0 = (sb & 3) * 16;

        for (int e = tid; e < Nn * 16; e += 256) {
            const int j  = e >> 4;
            const int kl = e & 15;
            const float v = x[(size_t)(b * Nn + j) * Kk + k0 + kl];
            const uint32_t u    = __float_as_uint(v);
            const uint32_t mono = (u & 0x80000000u) ? ~u : (u | 0x80000000u);
            ss[j][kl] = ((unsigned long long)mono << 32) | (uint32_t)j;
        }
        __syncthreads();

        for (int sz = 2; sz <= Nn; sz <<= 1) {
            for (int str = sz >> 1; str > 0; str >>= 1) {
                unsigned long long nv[8];
                #pragma unroll
                for (int p = 0; p < 8; ++p) {
                    const int e  = tid + 256 * p;
                    const int t  = e >> 4;
                    const int kl = e & 15;
                    const int tp = t ^ str;
                    const unsigned long long a = ss[t][kl];
                    const unsigned long long o = ss[tp][kl];
                    const bool desc = ((t & sz) == 0);
                    const unsigned long long lo = (a < o) ? a : o;
                    const unsigned long long hi = (a < o) ? o : a;
                    nv[p] = desc ? ((t < tp) ? hi : lo) : ((t < tp) ? lo : hi);
                }
                __syncthreads();
                #pragma unroll
                for (int p = 0; p < 8; ++p) {
                    const int e = tid + 256 * p;
                    ss[e >> 4][e & 15] = nv[p];
                }
                __syncthreads();
            }
        }

        // write out with mono decoded back to raw float bits
        for (int e = tid; e < Nn * 16; e += 256) {
            const int t  = e >> 4;
            const int kl = e & 15;
            const unsigned long long s = ss[t][kl];
            const uint32_t mono = (uint32_t)(s >> 32);
            const uint32_t u    = (mono & 0x80000000u) ? (mono & 0x7fffffffu) : ~mono;
            g_sorted[(size_t)(b * Nn + t) * Kk + k0 + kl] =
                ((unsigned long long)u << 32) | (uint32_t)(s & 0xffffffffu);
        }
    }
}

// ---------------------------------------------------------------------------
// Kernel 2: probe. Block = (b, 32-row i tile). Warp owns 4 i's; lane owns
// k = {lane, lane+32}; all 4 channels walked simultaneously per lane.
// ---------------------------------------------------------------------------
__global__ __launch_bounds__(256, 4)
void gmp_probe(float* __restrict__ out) {
    __shared__ unsigned long long sf[32][Kk];      // sorted front, 16 KB
    __shared__ uint32_t smw[Cc][32][4];            // mask words, 2 KB
    __shared__ uint8_t  sbits[32][Nn];             // 4-channel nibble per (i,j), 4 KB

    const int b    = blockIdx.x;
    const int i0   = blockIdx.y * 32;
    const int tid  = threadIdx.x;
    const int warp = tid >> 5;
    const int lane = tid & 31;

    // stage sorted front rows 0..31
    for (int e = tid; e < 32 * Kk; e += 256) {
        const int t = e >> 6, kk = e & 63;
        sf[t][kk] = g_sorted[(size_t)(b * Nn + t) * Kk + kk];
    }
    // stage mask words
    if (tid < 128) {
        const int c = tid >> 5, il = tid & 31;
        const uint4 mv = ((const uint4*)g_masks)[(size_t)((b * Cc + c) * Nn) + i0 + il];
        smw[c][il][0] = mv.x; smw[c][il][1] = mv.y; smw[c][il][2] = mv.z; smw[c][il][3] = mv.w;
    }
    __syncthreads();

    // build per-(i,j) channel nibbles
    for (int e = tid; e < 32 * Nn; e += 256) {
        const int il = e >> 7, j = e & 127;
        const int w = j >> 5, sh = j & 31;
        const uint8_t bt = (uint8_t)( ((smw[0][il][w] >> sh) & 1u)
                                    | (((smw[1][il][w] >> sh) & 1u) << 1)
                                    | (((smw[2][il][w] >> sh) & 1u) << 2)
                                    | (((smw[3][il][w] >> sh) & 1u) << 3) );
        sbits[il][j] = bt;
    }
    __syncthreads();

    #pragma unroll
    for (int r = 0; r < 4; ++r) {
        const int il = warp * 4 + r;
        const int i  = i0 + il;

        uint32_t fnd = 0;                      // bits 0..3: k0 channels, 4..7: k1
        float v0[4], v1[4];
        #pragma unroll
        for (int c = 0; c < 4; ++c) { v0[c] = -INFINITY; v1[c] = -INFINITY; }

        // hot loop over smem front
        int t = 0;
        while (t < 32) {
            const unsigned long long p0 = sf[t][lane];
            const unsigned long long p1 = sf[t][lane + 32];
            {
                const uint32_t j0 = (uint32_t)p0 & 127u;
                const float    xv = __uint_as_float((uint32_t)(p0 >> 32));
                const uint32_t nb = (uint32_t)sbits[il][j0] & 0xFu & ~fnd;
                v0[0] = (nb & 1u) ? xv : v0[0];
                v0[1] = (nb & 2u) ? xv : v0[1];
                v0[2] = (nb & 4u) ? xv : v0[2];
                v0[3] = (nb & 8u) ? xv : v0[3];
                fnd |= nb;
            }
            {
                const uint32_t j1 = (uint32_t)p1 & 127u;
                const float    xv = __uint_as_float((uint32_t)(p1 >> 32));
                const uint32_t nb = (uint32_t)sbits[il][j1] & 0xFu & ~(fnd >> 4);
                v1[0] = (nb & 1u) ? xv : v1[0];
                v1[1] = (nb & 2u) ? xv : v1[1];
                v1[2] = (nb & 4u) ? xv : v1[2];
                v1[3] = (nb & 8u) ? xv : v1[3];
                fnd |= nb << 4;
            }
            ++t;
            if (__all_sync(0xffffffffu, fnd == 0xFFu)) break;
        }
        // rare exact tail from global
        while (t < Nn && __any_sync(0xffffffffu, fnd != 0xFFu)) {
            const unsigned long long p0 = g_sorted[(size_t)(b * Nn + t) * Kk + lane];
            const unsigned long long p1 = g_sorted[(size_t)(b * Nn + t) * Kk + lane + 32];
            {
                const uint32_t j0 = (uint32_t)p0 & 127u;
                const float    xv = __uint_as_float((uint32_t)(p0 >> 32));
                const uint32_t nb = (uint32_t)sbits[il][j0] & 0xFu & ~fnd;
                v0[0] = (nb & 1u) ? xv : v0[0];
                v0[1] = (nb & 2u) ? xv : v0[1];
                v0[2] = (nb & 4u) ? xv : v0[2];
                v0[3] = (nb & 8u) ? xv : v0[3];
                fnd |= nb;
            }
            {
                const uint32_t j1 = (uint32_t)p1 & 127u;
                const float    xv = __uint_as_float((uint32_t)(p1 >> 32));
                const uint32_t nb = (uint32_t)sbits[il][j1] & 0xFu & ~(fnd >> 4);
                v1[0] = (nb & 1u) ? xv : v1[0];
                v1[1] = (nb & 2u) ? xv : v1[1];
                v1[2] = (nb & 4u) ? xv : v1[2];
                v1[3] = (nb & 8u) ? xv : v1[3];
                fnd |= nb << 4;
            }
            ++t;
        }

        // full-mask flags (uniform per i,c) and reference-order channel sum
        float a0 = 0.0f, a1 = 0.0f;
        bool first = true;
        #pragma unroll
        for (int c = 0; c < 4; ++c) {
            const int pc = __popc(smw[c][il][0]) + __popc(smw[c][il][1])
                         + __popc(smw[c][il][2]) + __popc(smw[c][il][3]);
            const bool full = (pc == Nn);
            const float r0 = full ? v0[c] : fmaxf(v0[c], 0.0f);
            const float r1 = full ? v1[c] : fmaxf(v1[c], 0.0f);
            if (first) { a0 = r0; a1 = r1; first = false; }
            else       { a0 = a0 + r0; a1 = a1 + r1; }
        }
        float* op = out + (size_t)(b * Nn + i) * Kk;
        op[lane]      = a0;
        op[lane + 32] = a1;
    }
}

extern "C" void kernel_launch(void* const* d_in, const int* in_sizes, int n_in,
                              void* d_out, int out_size) {
    const float* x;
    const float* adj;
    if (in_sizes[0] == Bb * Nn * Kk) { x = (const float*)d_in[0]; adj = (const float*)d_in[1]; }
    else                             { x = (const float*)d_in[1]; adj = (const float*)d_in[0]; }
    float* out = (float*)d_out;

    gmp_prep<<<1280, 256>>>(x, adj);
    gmp_probe<<<dim3(Bb, 4), 256>>>(out);
}